// round 1
// baseline (speedup 1.0000x reference)
#include <cuda_runtime.h>
#include <math.h>

#define N 4096
#define D 1024
#define DELTA 0.2f

// Scratch (allocation-free contract: __device__ globals)
__device__ float g_Xn[N * D];
__device__ float g_Yn[N * D];
__device__ float g_pos[N];
__device__ float g_partials[64 * 64];

// ---------------------------------------------------------------------------
// Kernel 1: row-normalize. blockIdx.x in [0, 2N): first N rows are X, rest Y.
// 256 threads, each handles 4 contiguous floats (D=1024).
// ---------------------------------------------------------------------------
__global__ void normalize_kernel(const float* __restrict__ X,
                                 const float* __restrict__ Y) {
    int row = blockIdx.x;
    const float* src;
    float* dst;
    if (row < N) { src = X + (size_t)row * D;        dst = g_Xn + (size_t)row * D; }
    else         { src = Y + (size_t)(row - N) * D;  dst = g_Yn + (size_t)(row - N) * D; }

    int tid = threadIdx.x;
    float4 v = *reinterpret_cast<const float4*>(src + tid * 4);
    float ss = v.x * v.x + v.y * v.y + v.z * v.z + v.w * v.w;

    // warp + block reduce
    #pragma unroll
    for (int off = 16; off > 0; off >>= 1)
        ss += __shfl_down_sync(0xFFFFFFFFu, ss, off);
    __shared__ float warp_sums[8];
    if ((tid & 31) == 0) warp_sums[tid >> 5] = ss;
    __syncthreads();
    __shared__ float s_scale;
    if (tid == 0) {
        float tot = 0.f;
        #pragma unroll
        for (int w = 0; w < 8; w++) tot += warp_sums[w];
        float nrm = sqrtf(tot);
        s_scale = 1.0f / fmaxf(nrm, 1e-8f);
    }
    __syncthreads();
    float sc = s_scale;
    float4 o = make_float4(v.x * sc, v.y * sc, v.z * sc, v.w * sc);
    *reinterpret_cast<float4*>(dst + tid * 4) = o;
}

// ---------------------------------------------------------------------------
// Kernel 2: pos[i] = dot(Xn_i, Yn_i)  (exact fp32 diagonal)
// ---------------------------------------------------------------------------
__global__ void pos_kernel() {
    int row = blockIdx.x;
    int tid = threadIdx.x;
    const float* xr = g_Xn + (size_t)row * D;
    const float* yr = g_Yn + (size_t)row * D;
    float4 a = *reinterpret_cast<const float4*>(xr + tid * 4);
    float4 b = *reinterpret_cast<const float4*>(yr + tid * 4);
    float s = a.x * b.x + a.y * b.y + a.z * b.z + a.w * b.w;
    #pragma unroll
    for (int off = 16; off > 0; off >>= 1)
        s += __shfl_down_sync(0xFFFFFFFFu, s, off);
    __shared__ float warp_sums[8];
    if ((tid & 31) == 0) warp_sums[tid >> 5] = s;
    __syncthreads();
    if (tid == 0) {
        float tot = 0.f;
        #pragma unroll
        for (int w = 0; w < 8; w++) tot += warp_sums[w];
        g_pos[row] = tot;
    }
}

// ---------------------------------------------------------------------------
// Kernel 3: 64x64 tile of S = Xn * Yn^T, fused hinge + diagonal mask +
// block-level reduction into g_partials[blockIdx]. BK=16, 256 threads,
// 4x4 micro-tile per thread, float4 shared reads.
// ---------------------------------------------------------------------------
__global__ void __launch_bounds__(256)
gemm_hinge_kernel() {
    const int bm = blockIdx.y * 64;
    const int bn = blockIdx.x * 64;
    const int tid = threadIdx.x;
    const int tx = tid & 15;   // column group
    const int ty = tid >> 4;   // row group

    __shared__ float As[16][64];   // [k][m]
    __shared__ float Bs[16][64];   // [k][n]

    float acc[4][4];
    #pragma unroll
    for (int r = 0; r < 4; r++)
        #pragma unroll
        for (int c = 0; c < 4; c++) acc[r][c] = 0.f;

    const int lrow = tid >> 2;        // 0..63
    const int lk   = (tid & 3) * 4;   // 0,4,8,12

    for (int k0 = 0; k0 < D; k0 += 16) {
        float4 a = *reinterpret_cast<const float4*>(g_Xn + (size_t)(bm + lrow) * D + k0 + lk);
        float4 b = *reinterpret_cast<const float4*>(g_Yn + (size_t)(bn + lrow) * D + k0 + lk);
        As[lk + 0][lrow] = a.x; As[lk + 1][lrow] = a.y;
        As[lk + 2][lrow] = a.z; As[lk + 3][lrow] = a.w;
        Bs[lk + 0][lrow] = b.x; Bs[lk + 1][lrow] = b.y;
        Bs[lk + 2][lrow] = b.z; Bs[lk + 3][lrow] = b.w;
        __syncthreads();

        #pragma unroll
        for (int kk = 0; kk < 16; kk++) {
            float4 av = *reinterpret_cast<const float4*>(&As[kk][ty * 4]);
            float4 bv = *reinterpret_cast<const float4*>(&Bs[kk][tx * 4]);
            float am[4] = {av.x, av.y, av.z, av.w};
            float bm_[4] = {bv.x, bv.y, bv.z, bv.w};
            #pragma unroll
            for (int r = 0; r < 4; r++)
                #pragma unroll
                for (int c = 0; c < 4; c++)
                    acc[r][c] = fmaf(am[r], bm_[c], acc[r][c]);
        }
        __syncthreads();
    }

    // Fused epilogue: hinge + diagonal mask + thread-local sum
    float psum = 0.f;
    #pragma unroll
    for (int r = 0; r < 4; r++) {
        int gi = bm + ty * 4 + r;
        float p = g_pos[gi];
        #pragma unroll
        for (int c = 0; c < 4; c++) {
            int gj = bn + tx * 4 + c;
            float h = fmaxf(0.f, DELTA - p + acc[r][c]);
            psum += (gi != gj) ? h : 0.f;
        }
    }

    // block reduction
    #pragma unroll
    for (int off = 16; off > 0; off >>= 1)
        psum += __shfl_down_sync(0xFFFFFFFFu, psum, off);
    __shared__ float warp_sums[8];
    if ((tid & 31) == 0) warp_sums[tid >> 5] = psum;
    __syncthreads();
    if (tid == 0) {
        float tot = 0.f;
        #pragma unroll
        for (int w = 0; w < 8; w++) tot += warp_sums[w];
        g_partials[blockIdx.y * gridDim.x + blockIdx.x] = tot;
    }
}

// ---------------------------------------------------------------------------
// Kernel 4: deterministic final reduction of 4096 partials.
// ---------------------------------------------------------------------------
__global__ void reduce_kernel(float* __restrict__ out) {
    int tid = threadIdx.x;
    float s = 0.f;
    #pragma unroll
    for (int i = tid; i < 64 * 64; i += 256) s += g_partials[i];
    #pragma unroll
    for (int off = 16; off > 0; off >>= 1)
        s += __shfl_down_sync(0xFFFFFFFFu, s, off);
    __shared__ float warp_sums[8];
    if ((tid & 31) == 0) warp_sums[tid >> 5] = s;
    __syncthreads();
    if (tid == 0) {
        float tot = 0.f;
        #pragma unroll
        for (int w = 0; w < 8; w++) tot += warp_sums[w];
        out[0] = tot;
    }
}

extern "C" void kernel_launch(void* const* d_in, const int* in_sizes, int n_in,
                              void* d_out, int out_size) {
    const float* X = (const float*)d_in[0];
    const float* Y = (const float*)d_in[1];
    float* out = (float*)d_out;

    normalize_kernel<<<2 * N, 256>>>(X, Y);
    pos_kernel<<<N, 256>>>();
    dim3 grid(64, 64);
    gemm_hinge_kernel<<<grid, 256>>>();
    reduce_kernel<<<1, 256>>>(out);
}

// round 3
// speedup vs baseline: 8.9414x; 8.9414x over previous
#include <cuda_runtime.h>
#include <cuda_bf16.h>
#include <cstdint>
#include <math.h>

#define NROWS 4096
#define DDIM  1024
#define DELTA 0.2f

#define TILE_M 128
#define TILE_N 256
#define KC     64                    // K elems per pipeline chunk (128 B/row bf16)
#define NCHUNK (DDIM / KC)           // 16
#define STAGES 4

#define GRID_M (NROWS / TILE_M)      // 32
#define GRID_N (NROWS / TILE_N)      // 16
#define NUM_TILES (GRID_M * GRID_N)  // 512

#define A_BYTES     (TILE_M * 128)           // 16384
#define B_BYTES     (TILE_N * 128)           // 32768
#define STAGE_BYTES (A_BYTES + B_BYTES)      // 49152
#define SMEM_TOTAL  (STAGES * STAGE_BYTES)   // 196608 (<= 227KB)

// Scratch (allocation-free contract)
__device__ __nv_bfloat16 g_Xb[NROWS * DDIM];
__device__ __nv_bfloat16 g_Yb[NROWS * DDIM];
__device__ float g_pos[NROWS];
__device__ float g_partials[NUM_TILES];

// ---------------------------------------------------------------------------
// helpers
// ---------------------------------------------------------------------------
__device__ __forceinline__ uint32_t smem_u32(const void* p) {
    uint32_t a;
    asm("{ .reg .u64 t; cvta.to.shared.u64 t, %1; cvt.u32.u64 %0, t; }" : "=r"(a) : "l"(p));
    return a;
}
#define SW128(o) ((o) ^ (((o) >> 3) & 0x70))

#define CP_ASYNC_16(dst_u32, src_ptr) \
    asm volatile("cp.async.cg.shared.global [%0], [%1], 16;" :: "r"(dst_u32), "l"(src_ptr))
#define CP_ASYNC_COMMIT() asm volatile("cp.async.commit_group;" ::: "memory")
#define CP_ASYNC_WAIT_2() asm volatile("cp.async.wait_group 2;" ::: "memory")

__device__ __forceinline__ void ldsm_x4(uint32_t* r, uint32_t addr) {
    asm volatile("ldmatrix.sync.aligned.m8n8.x4.shared.b16 {%0,%1,%2,%3}, [%4];"
                 : "=r"(r[0]), "=r"(r[1]), "=r"(r[2]), "=r"(r[3]) : "r"(addr));
}
__device__ __forceinline__ void mma_bf16(float* c, const uint32_t* a, const uint32_t* b) {
    asm volatile(
        "mma.sync.aligned.m16n8k16.row.col.f32.bf16.bf16.f32 "
        "{%0,%1,%2,%3}, {%4,%5,%6,%7}, {%8,%9}, {%0,%1,%2,%3};"
        : "+f"(c[0]), "+f"(c[1]), "+f"(c[2]), "+f"(c[3])
        : "r"(a[0]), "r"(a[1]), "r"(a[2]), "r"(a[3]), "r"(b[0]), "r"(b[1]));
}

// ---------------------------------------------------------------------------
// Kernel 1: fused normalize (fp32->bf16) + exact fp32 pos. One block per row.
// ---------------------------------------------------------------------------
__global__ void __launch_bounds__(256) normalize_kernel(const float* __restrict__ X,
                                                        const float* __restrict__ Y) {
    int row = blockIdx.x;
    int tid = threadIdx.x;
    const float4* xr = reinterpret_cast<const float4*>(X + (size_t)row * DDIM);
    const float4* yr = reinterpret_cast<const float4*>(Y + (size_t)row * DDIM);
    float4 xv = xr[tid];
    float4 yv = yr[tid];
    float ssx = xv.x * xv.x + xv.y * xv.y + xv.z * xv.z + xv.w * xv.w;
    float ssy = yv.x * yv.x + yv.y * yv.y + yv.z * yv.z + yv.w * yv.w;
    float sxy = xv.x * yv.x + xv.y * yv.y + xv.z * yv.z + xv.w * yv.w;

    #pragma unroll
    for (int off = 16; off > 0; off >>= 1) {
        ssx += __shfl_down_sync(0xFFFFFFFFu, ssx, off);
        ssy += __shfl_down_sync(0xFFFFFFFFu, ssy, off);
        sxy += __shfl_down_sync(0xFFFFFFFFu, sxy, off);
    }
    __shared__ float wx[8], wy[8], wxy[8];
    __shared__ float s_sx, s_sy;
    if ((tid & 31) == 0) { wx[tid >> 5] = ssx; wy[tid >> 5] = ssy; wxy[tid >> 5] = sxy; }
    __syncthreads();
    if (tid == 0) {
        float tx = 0.f, ty = 0.f, txy = 0.f;
        #pragma unroll
        for (int w = 0; w < 8; w++) { tx += wx[w]; ty += wy[w]; txy += wxy[w]; }
        float sx = 1.0f / fmaxf(sqrtf(tx), 1e-8f);
        float sy = 1.0f / fmaxf(sqrtf(ty), 1e-8f);
        s_sx = sx; s_sy = sy;
        g_pos[row] = txy * sx * sy;
    }
    __syncthreads();
    float sx = s_sx, sy = s_sy;
    __nv_bfloat162* dx = reinterpret_cast<__nv_bfloat162*>(g_Xb + (size_t)row * DDIM);
    __nv_bfloat162* dy = reinterpret_cast<__nv_bfloat162*>(g_Yb + (size_t)row * DDIM);
    dx[tid * 2 + 0] = __floats2bfloat162_rn(xv.x * sx, xv.y * sx);
    dx[tid * 2 + 1] = __floats2bfloat162_rn(xv.z * sx, xv.w * sx);
    dy[tid * 2 + 0] = __floats2bfloat162_rn(yv.x * sy, yv.y * sy);
    dy[tid * 2 + 1] = __floats2bfloat162_rn(yv.z * sy, yv.w * sy);
}

// ---------------------------------------------------------------------------
// Kernel 2: bf16 mma.sync GEMM (128x256 CTA tile) + fused hinge epilogue.
// 8 warps in 2(m) x 4(n); warp tile 64x64 => acc[4][8][4] per thread.
// ---------------------------------------------------------------------------
__global__ void __launch_bounds__(256, 1) gemm_hinge_kernel() {
    extern __shared__ char smem[];
    const uint32_t sb = smem_u32(smem);
    const int tid  = threadIdx.x;
    const int wid  = tid >> 5;
    const int lane = tid & 31;
    const int warp_m = wid & 1;          // 0..1
    const int warp_n = wid >> 1;         // 0..3
    const int bm = blockIdx.y * TILE_M;
    const int bn = blockIdx.x * TILE_N;

    float acc[4][8][4];
    #pragma unroll
    for (int i = 0; i < 4; i++)
        #pragma unroll
        for (int j = 0; j < 8; j++)
            #pragma unroll
            for (int e = 0; e < 4; e++) acc[i][j][e] = 0.f;

    // cp.async chunk loader: chunk j -> stage s
    const int ld_row = tid >> 3;          // 0..31
    const int ld_c   = tid & 7;           // 16B column
    auto load_chunk = [&](int j, int s) {
        const uint32_t stage = sb + s * STAGE_BYTES;
        const int k0 = j * KC;
        #pragma unroll
        for (int q = 0; q < 4; q++) {     // A: 128 rows
            int row = ld_row + q * 32;
            const __nv_bfloat16* src = g_Xb + (size_t)(bm + row) * DDIM + k0 + ld_c * 8;
            uint32_t off = (uint32_t)(row * 128 + ld_c * 16);
            CP_ASYNC_16(stage + SW128(off), src);
        }
        #pragma unroll
        for (int q = 0; q < 8; q++) {     // B: 256 rows
            int row = ld_row + q * 32;
            const __nv_bfloat16* src = g_Yb + (size_t)(bn + row) * DDIM + k0 + ld_c * 8;
            uint32_t off = (uint32_t)(row * 128 + ld_c * 16);
            CP_ASYNC_16(stage + A_BYTES + SW128(off), src);
        }
    };

    // prologue: 3 stages in flight
    #pragma unroll
    for (int j = 0; j < STAGES - 1; j++) {
        load_chunk(j, j);
        CP_ASYNC_COMMIT();
    }

    // ldmatrix per-lane row components (constant across loop)
    const int a_row_l = (lane & 15);                       // within 16-row tile
    const int a_kb_l  = (lane >> 4) << 4;                  // 0 or 16 bytes
    const int b_row_l = (lane & 7) + ((lane >> 4) << 3);   // within 16-row pair
    const int b_kb_l  = ((lane >> 3) & 1) << 4;            // 0 or 16 bytes

    for (int j = 0; j < NCHUNK; j++) {
        const int s = j & (STAGES - 1);
        CP_ASYNC_WAIT_2();
        __syncthreads();
        if (j + STAGES - 1 < NCHUNK) load_chunk(j + STAGES - 1, (j + STAGES - 1) & (STAGES - 1));
        CP_ASYNC_COMMIT();

        const uint32_t Abase = sb + s * STAGE_BYTES;
        const uint32_t Bbase = Abase + A_BYTES;

        #pragma unroll
        for (int kk = 0; kk < 4; kk++) {
            const int kb = kk * 32;
            uint32_t afr[4][4];
            #pragma unroll
            for (int im = 0; im < 4; im++) {
                int row = warp_m * 64 + im * 16 + a_row_l;
                uint32_t off = (uint32_t)(row * 128 + kb + a_kb_l);
                ldsm_x4(afr[im], Abase + SW128(off));
            }
            uint32_t bfr[4][4];
            #pragma unroll
            for (int jn = 0; jn < 4; jn++) {
                int row = warp_n * 64 + jn * 16 + b_row_l;
                uint32_t off = (uint32_t)(row * 128 + kb + b_kb_l);
                ldsm_x4(bfr[jn], Bbase + SW128(off));
            }
            #pragma unroll
            for (int im = 0; im < 4; im++) {
                #pragma unroll
                for (int jn = 0; jn < 4; jn++) {
                    mma_bf16(acc[im][2 * jn],     afr[im], &bfr[jn][0]);
                    mma_bf16(acc[im][2 * jn + 1], afr[im], &bfr[jn][2]);
                }
            }
        }
    }

    // Fused epilogue: hinge + diagonal mask + local sum
    float psum = 0.f;
    #pragma unroll
    for (int im = 0; im < 4; im++) {
        const int r0 = bm + warp_m * 64 + im * 16 + (lane >> 2);
        const int r1 = r0 + 8;
        const float p0 = __ldg(&g_pos[r0]);
        const float p1 = __ldg(&g_pos[r1]);
        #pragma unroll
        for (int t = 0; t < 8; t++) {
            const int c0 = bn + warp_n * 64 + t * 8 + (lane & 3) * 2;
            const int c1 = c0 + 1;
            float h;
            h = fmaxf(0.f, DELTA - p0 + acc[im][t][0]); psum += (r0 != c0) ? h : 0.f;
            h = fmaxf(0.f, DELTA - p0 + acc[im][t][1]); psum += (r0 != c1) ? h : 0.f;
            h = fmaxf(0.f, DELTA - p1 + acc[im][t][2]); psum += (r1 != c0) ? h : 0.f;
            h = fmaxf(0.f, DELTA - p1 + acc[im][t][3]); psum += (r1 != c1) ? h : 0.f;
        }
    }

    #pragma unroll
    for (int off = 16; off > 0; off >>= 1)
        psum += __shfl_down_sync(0xFFFFFFFFu, psum, off);
    __shared__ float warp_sums[8];
    if (lane == 0) warp_sums[wid] = psum;
    __syncthreads();
    if (tid == 0) {
        float tot = 0.f;
        #pragma unroll
        for (int w = 0; w < 8; w++) tot += warp_sums[w];
        g_partials[blockIdx.y * GRID_N + blockIdx.x] = tot;
    }
}

// ---------------------------------------------------------------------------
// Kernel 3: final deterministic reduction over 512 partials.
// ---------------------------------------------------------------------------
__global__ void __launch_bounds__(256) reduce_kernel(float* __restrict__ out) {
    int tid = threadIdx.x;
    float s = 0.f;
    #pragma unroll
    for (int i = tid; i < NUM_TILES; i += 256) s += g_partials[i];
    #pragma unroll
    for (int off = 16; off > 0; off >>= 1)
        s += __shfl_down_sync(0xFFFFFFFFu, s, off);
    __shared__ float warp_sums[8];
    if ((tid & 31) == 0) warp_sums[tid >> 5] = s;
    __syncthreads();
    if (tid == 0) {
        float tot = 0.f;
        #pragma unroll
        for (int w = 0; w < 8; w++) tot += warp_sums[w];
        out[0] = tot;
    }
}

extern "C" void kernel_launch(void* const* d_in, const int* in_sizes, int n_in,
                              void* d_out, int out_size) {
    const float* X = (const float*)d_in[0];
    const float* Y = (const float*)d_in[1];
    float* out = (float*)d_out;

    cudaFuncSetAttribute(gemm_hinge_kernel,
                         cudaFuncAttributeMaxDynamicSharedMemorySize, SMEM_TOTAL);

    normalize_kernel<<<NROWS, 256>>>(X, Y);
    dim3 grid(GRID_N, GRID_M);
    gemm_hinge_kernel<<<grid, 256, SMEM_TOTAL>>>();
    reduce_kernel<<<1, 256>>>(out);
}